// round 15
// baseline (speedup 1.0000x reference)
#include <cuda_runtime.h>
#include <cuda_bf16.h>
#include <math.h>
#include <stdint.h>

#define NNODES 20000
#define NEDGES 320000
#define HD 128
#define OUT_OE (NNODES * HD)

// ---------------- scratch ----------------------------------------------------
__device__ float g_Q[NNODES * HD];
__device__ float g_K[NNODES * HD];
__device__ float g_V[NNODES * HD];
__device__ float g_w[NEDGES * 8];
__device__ int   g_deg[NNODES];
__device__ int   g_off[NNODES + 1];
__device__ int   g_cursor[NNODES];
__device__ int2  g_csr[NEDGES];
#define SCAN_BLK 256
#define NSCB ((NNODES + SCAN_BLK - 1) / SCAN_BLK)
__device__ int   g_bsum[NSCB];
__device__ int   g_bpre[NSCB];
// pre-swizzled bf16 images
__device__ unsigned long long g_Bh[4096];        // Ew hi: [64 k][256 n], 32KB
__device__ unsigned long long g_Bl[4096];        // Ew lo
__device__ unsigned long long g_Wh[3 * 2048];    // Qw/Kw/Vw hi
__device__ unsigned long long g_Wl[3 * 2048];    // Qw/Kw/Vw lo

// ---------------- helpers ----------------------------------------------------
__device__ __forceinline__ uint32_t smem_u32(const void* p) {
    uint32_t a;
    asm("{ .reg .u64 t; cvta.to.shared.u64 t, %1; cvt.u32.u64 %0, t; }" : "=r"(a) : "l"(p));
    return a;
}
__device__ __forceinline__ unsigned long long pack4_hi(float4 v) {
    unsigned short h0 = __bfloat16_as_ushort(__float2bfloat16(v.x));
    unsigned short h1 = __bfloat16_as_ushort(__float2bfloat16(v.y));
    unsigned short h2 = __bfloat16_as_ushort(__float2bfloat16(v.z));
    unsigned short h3 = __bfloat16_as_ushort(__float2bfloat16(v.w));
    return (unsigned long long)h0 | ((unsigned long long)h1 << 16) |
           ((unsigned long long)h2 << 32) | ((unsigned long long)h3 << 48);
}
__device__ __forceinline__ float4 resid4(float4 v) {
    return make_float4(
        v.x - __bfloat162float(__float2bfloat16(v.x)),
        v.y - __bfloat162float(__float2bfloat16(v.y)),
        v.z - __bfloat162float(__float2bfloat16(v.z)),
        v.w - __bfloat162float(__float2bfloat16(v.w)));
}
__device__ __forceinline__ void ldmatrix_x4(uint32_t* r, uint32_t addr) {
    asm volatile("ldmatrix.sync.aligned.m8n8.x4.shared.b16 {%0,%1,%2,%3}, [%4];"
                 : "=r"(r[0]), "=r"(r[1]), "=r"(r[2]), "=r"(r[3]) : "r"(addr));
}
__device__ __forceinline__ void ldmatrix_x4t(uint32_t* r, uint32_t addr) {
    asm volatile("ldmatrix.sync.aligned.m8n8.x4.trans.shared.b16 {%0,%1,%2,%3}, [%4];"
                 : "=r"(r[0]), "=r"(r[1]), "=r"(r[2]), "=r"(r[3]) : "r"(addr));
}
__device__ __forceinline__ void mma16816(float* c, const uint32_t* a, const uint32_t* b) {
    asm volatile(
        "mma.sync.aligned.m16n8k16.row.col.f32.bf16.bf16.f32 "
        "{%0,%1,%2,%3}, {%4,%5,%6,%7}, {%8,%9}, {%0,%1,%2,%3};"
        : "+f"(c[0]), "+f"(c[1]), "+f"(c[2]), "+f"(c[3])
        : "r"(a[0]), "r"(a[1]), "r"(a[2]), "r"(a[3]), "r"(b[0]), "r"(b[1]));
}
__device__ __forceinline__ float sqrt_approx(float x) {
    float r;
    asm("sqrt.approx.f32 %0, %1;" : "=f"(r) : "f"(x));
    return r;
}

// ---------------- K0a: Ew -> bf16 hi/lo pre-swizzled image [64][256] --------
__global__ void bprep_kernel(const float* __restrict__ Ew)
{
    const int jb = blockIdx.x;    // 0..3
    const int t  = threadIdx.x;   // 256
    #pragma unroll
    for (int it = 0; it < 4; it++) {
        int idx = it * 256 + t;
        int k   = idx >> 4;
        int n4l = (idx & 15) * 4;
        int n   = jb * 64 + n4l;
        const float* p = Ew + (size_t)k * 256 + n;
        float4 v = make_float4(p[0], p[1], p[2], p[3]);
        unsigned int byte = (unsigned)k * 512 + (((unsigned)n * 2) ^ (((unsigned)k & 7) << 4));
        g_Bh[byte >> 3] = pack4_hi(v);
        g_Bl[byte >> 3] = pack4_hi(resid4(v));
    }
}

// ---------------- K0b: Qw/Kw/Vw -> bf16 hi/lo images [64][128] each ---------
__global__ void wprep_kernel(const float* __restrict__ Qw,
                             const float* __restrict__ Kw,
                             const float* __restrict__ Vw)
{
    const int sel = blockIdx.x;   // 0..2
    const float* W = (sel == 0) ? Qw : ((sel == 1) ? Kw : Vw);
    const int t = threadIdx.x;    // 256
    #pragma unroll
    for (int it = 0; it < 8; it++) {
        int idx = it * 256 + t;
        int k   = idx >> 5;
        int n4  = (idx & 31) * 4;
        const float* p = W + (size_t)k * 128 + n4;
        float4 v = make_float4(p[0], p[1], p[2], p[3]);
        unsigned int byte = (unsigned)k * 256 + (((unsigned)n4 * 2) ^ (((unsigned)k & 7) << 4));
        unsigned int i8 = ((unsigned)sel * 16384 + byte) >> 3;
        g_Wh[i8] = pack4_hi(v);
        g_Wl[i8] = pack4_hi(resid4(v));
    }
}

// ---------------- K1: QKV node GEMM via mma.sync bf16 hi/lo (3-term) --------
// selofs: 0 -> blockIdx.y in {0,1} = Q,K (main stream); 2 -> V (side stream)
#define QSM_A_HI 0
#define QSM_A_LO 16384
#define QSM_B_HI 32768
#define QSM_B_LO 49152
#define SMEM_QKV_TOTAL 65536

__global__ __launch_bounds__(512, 2) void qkv_kernel(
    const float* __restrict__ x,
    const float* __restrict__ Qb, const float* __restrict__ Kb,
    const float* __restrict__ Vb, int selofs)
{
    extern __shared__ char smem[];
    const uint32_t sbase = smem_u32(smem);
    const int t   = threadIdx.x;
    const int l   = t & 31;
    const int w   = t >> 5;
    const int m0  = blockIdx.x * 128;
    const int sel = blockIdx.y + selofs;
    const float* Bv = (sel == 0) ? Qb : ((sel == 1) ? Kb : Vb);
    float* out      = (sel == 0) ? g_Q : ((sel == 1) ? g_K : g_V);

    #pragma unroll
    for (int it = 0; it < 4; it++) {
        int idx = it * 512 + t;
        int row = idx >> 4;
        int c4  = (idx & 15) * 4;
        float4 v = make_float4(0.f, 0.f, 0.f, 0.f);
        if (m0 + row < NNODES) v = *(const float4*)(x + (size_t)(m0 + row) * 64 + c4);
        unsigned int byte = (unsigned)row * 128 + (((unsigned)c4 * 2) ^ (((unsigned)row & 7) << 4));
        *(unsigned long long*)(smem + QSM_A_HI + byte) = pack4_hi(v);
        *(unsigned long long*)(smem + QSM_A_LO + byte) = pack4_hi(resid4(v));
    }
    {
        const ulonglong2* bh = (const ulonglong2*)(g_Wh + sel * 2048);
        const ulonglong2* bl = (const ulonglong2*)(g_Wl + sel * 2048);
        ulonglong2* dh = (ulonglong2*)(smem + QSM_B_HI);
        ulonglong2* dl = (ulonglong2*)(smem + QSM_B_LO);
        #pragma unroll
        for (int it = 0; it < 2; it++) {
            int idx = it * 512 + t;
            dh[idx] = bh[idx];
            dl[idx] = bl[idx];
        }
    }
    __syncthreads();

    const int rg   = w >> 2;
    const int cg   = w & 3;
    const int g    = l >> 2;
    const int t2   = (l & 3) * 2;
    const int lx   = l & 7;
    const int bl15 = l & 15;
    const int jhi  = l >> 4;
    const int arow = rg * 32 + (l & 15);
    const int asw  = ((l & 15) & 7) << 4;

    float acc[2][4][4];
    #pragma unroll
    for (int m = 0; m < 2; m++)
        #pragma unroll
        for (int n = 0; n < 4; n++)
            #pragma unroll
            for (int q = 0; q < 4; q++) acc[m][n][q] = 0.f;

    #pragma unroll
    for (int ks = 0; ks < 4; ks++) {
        uint32_t ah[2][4], al[2][4];
        #pragma unroll
        for (int m = 0; m < 2; m++) {
            uint32_t aoff = (unsigned)(arow + m * 16) * 128 +
                            (((unsigned)(32 * ks + (l & 16))) ^ (unsigned)asw);
            ldmatrix_x4(ah[m], sbase + QSM_A_HI + aoff);
            ldmatrix_x4(al[m], sbase + QSM_A_LO + aoff);
        }
        uint32_t browoff = (unsigned)(16 * ks + bl15) * 256;
        #pragma unroll
        for (int np = 0; np < 2; np++) {
            uint32_t boff = ((unsigned)((cg * 4 + np * 2 + jhi) ^ lx)) << 4;
            uint32_t bh[4], blo[4];
            ldmatrix_x4t(bh,  sbase + QSM_B_HI + browoff + boff);
            ldmatrix_x4t(blo, sbase + QSM_B_LO + browoff + boff);
            #pragma unroll
            for (int m = 0; m < 2; m++) {
                mma16816(acc[m][np * 2],     ah[m], bh);
                mma16816(acc[m][np * 2 + 1], ah[m], bh + 2);
                mma16816(acc[m][np * 2],     al[m], bh);
                mma16816(acc[m][np * 2 + 1], al[m], bh + 2);
                mma16816(acc[m][np * 2],     ah[m], blo);
                mma16816(acc[m][np * 2 + 1], ah[m], blo + 2);
            }
        }
    }

    float2 bias[4];
    #pragma unroll
    for (int n = 0; n < 4; n++) {
        int col = cg * 32 + n * 8 + t2;
        bias[n] = make_float2(__ldg(Bv + col), __ldg(Bv + col + 1));
    }
    #pragma unroll
    for (int m = 0; m < 2; m++) {
        int row0 = m0 + rg * 32 + m * 16 + g;
        #pragma unroll
        for (int n = 0; n < 4; n++) {
            int col = cg * 32 + n * 8 + t2;
            if (row0 < NNODES)
                *(float2*)(out + (size_t)row0 * HD + col) =
                    make_float2(acc[m][n][0] + bias[n].x, acc[m][n][1] + bias[n].y);
            if (row0 + 8 < NNODES)
                *(float2*)(out + (size_t)(row0 + 8) * HD + col) =
                    make_float2(acc[m][n][2] + bias[n].x, acc[m][n][3] + bias[n].y);
        }
    }
}

// ---------------- K2: edge GEMM, BN=256 (all 8 heads), reg epilogue ---------
// 1024 threads / 32 warps; warp = 32 rows x 1 head. 3-term hi/lo split.
#define SM_A_HI 0
#define SM_A_LO 16384
#define SM_B_HI 32768
#define SM_B_LO 65536
#define SMEM_EDGE_TOTAL 98304

__global__ __launch_bounds__(1024, 1) void edge_kernel(
    const float* __restrict__ eattr, const int* __restrict__ eidx,
    const float* __restrict__ Eb, const float* __restrict__ Aw,
    float* __restrict__ outbuf)
{
    extern __shared__ char smem[];
    const uint32_t sbase = smem_u32(smem);
    const int t   = threadIdx.x;
    const int l   = t & 31;
    const int w   = t >> 5;
    const int m0  = blockIdx.x * 128;

    // ---- A tile: 128 edges x 64 K -> hi/lo bf16, swizzled (128B rows)
    #pragma unroll
    for (int it = 0; it < 2; it++) {
        int idx = it * 1024 + t;
        int row = idx >> 4;
        int c4  = (idx & 15) * 4;
        float4 v = __ldcs((const float4*)(eattr + (size_t)(m0 + row) * 64 + c4));
        unsigned int byte = (unsigned)row * 128 + (((unsigned)c4 * 2) ^ (((unsigned)row & 7) << 4));
        *(unsigned long long*)(smem + SM_A_HI + byte) = pack4_hi(v);
        *(unsigned long long*)(smem + SM_A_LO + byte) = pack4_hi(resid4(v));
    }
    // ---- B image copy (32KB each)
    {
        const ulonglong2* bh = (const ulonglong2*)g_Bh;
        const ulonglong2* bl = (const ulonglong2*)g_Bl;
        ulonglong2* dh = (ulonglong2*)(smem + SM_B_HI);
        ulonglong2* dl = (ulonglong2*)(smem + SM_B_LO);
        #pragma unroll
        for (int it = 0; it < 2; it++) {
            int idx = it * 1024 + t;
            dh[idx] = bh[idx];
            dl[idx] = bl[idx];
        }
    }
    __syncthreads();

    // ---- MMA: warp w -> rows 32*(w>>3)..+31, head (w&7)
    const int rg   = w >> 3;
    const int cg   = w & 7;
    const int g    = l >> 2;
    const int t2   = (l & 3) * 2;
    const int lx   = l & 7;
    const int bl15 = l & 15;
    const int jhi  = l >> 4;
    const int arow = rg * 32 + (l & 15);
    const int asw  = ((l & 15) & 7) << 4;

    float acc[2][4][4];
    #pragma unroll
    for (int m = 0; m < 2; m++)
        #pragma unroll
        for (int n = 0; n < 4; n++)
            #pragma unroll
            for (int q = 0; q < 4; q++) acc[m][n][q] = 0.f;

    #pragma unroll
    for (int ks = 0; ks < 4; ks++) {
        uint32_t ah[2][4], al[2][4];
        #pragma unroll
        for (int m = 0; m < 2; m++) {
            uint32_t aoff = (unsigned)(arow + m * 16) * 128 +
                            (((unsigned)(32 * ks + (l & 16))) ^ (unsigned)asw);
            ldmatrix_x4(ah[m], sbase + SM_A_HI + aoff);
            ldmatrix_x4(al[m], sbase + SM_A_LO + aoff);
        }
        uint32_t browoff = (unsigned)(16 * ks + bl15) * 512;   // 512B rows (256 cols)
        #pragma unroll
        for (int np = 0; np < 2; np++) {
            uint32_t boff = ((unsigned)((cg * 4 + np * 2 + jhi) ^ lx)) << 4;
            uint32_t bh[4], blo[4];
            ldmatrix_x4t(bh,  sbase + SM_B_HI + browoff + boff);
            ldmatrix_x4t(blo, sbase + SM_B_LO + browoff + boff);
            #pragma unroll
            for (int m = 0; m < 2; m++) {
                mma16816(acc[m][np * 2],     ah[m], bh);
                mma16816(acc[m][np * 2 + 1], ah[m], bh + 2);
                mma16816(acc[m][np * 2],     al[m], bh);
                mma16816(acc[m][np * 2 + 1], al[m], bh + 2);
                mma16816(acc[m][np * 2],     ah[m], blo);
                mma16816(acc[m][np * 2 + 1], ah[m], blo + 2);
            }
        }
    }

    // ---- epilogue (in registers) ----
    const int h    = cg;
    const int colK = h * 16;

    // hoist index loads (better MLP over the gather latency)
    int srcs[4], dsts[4];
    #pragma unroll
    for (int r = 0; r < 4; r++) {
        const int e = m0 + rg * 32 + (r >> 1) * 16 + g + (r & 1) * 8;
        srcs[r] = eidx[e];
        dsts[r] = eidx[NEDGES + e];
    }

    const float eb1a = __ldg(Eb + h * 32 + t2);
    const float eb1b = __ldg(Eb + h * 32 + t2 + 1);
    const float eb1c = __ldg(Eb + h * 32 + 8 + t2);
    const float eb1d = __ldg(Eb + h * 32 + 8 + t2 + 1);
    const float eb2a = __ldg(Eb + h * 32 + 16 + t2);
    const float eb2b = __ldg(Eb + h * 32 + 16 + t2 + 1);
    const float eb2c = __ldg(Eb + h * 32 + 24 + t2);
    const float eb2d = __ldg(Eb + h * 32 + 24 + t2 + 1);
    const float aw0 = __ldg(Aw + (t2)     * 8 + h);
    const float aw1 = __ldg(Aw + (t2 + 1) * 8 + h);
    const float aw8 = __ldg(Aw + (8 + t2)     * 8 + h);
    const float aw9 = __ldg(Aw + (8 + t2 + 1) * 8 + h);

    float apart[4];
    #pragma unroll
    for (int r = 0; r < 4; r++) {
        const int m  = r >> 1;
        const int qh = r & 1;
        const int e  = m0 + rg * 32 + m * 16 + g + qh * 8;
        const float* Krow = g_K + (size_t)srcs[r] * HD + colK;
        const float* Qrow = g_Q + (size_t)dsts[r] * HD + colK;
        float* oEp = outbuf + (size_t)OUT_OE + (size_t)e * HD + colK;

        float a = 0.f;
        {
            float s1a = acc[m][0][qh * 2]     + eb1a;
            float s1b = acc[m][0][qh * 2 + 1] + eb1b;
            float s2a = acc[m][2][qh * 2]     + eb2a;
            float s2b = acc[m][2][qh * 2 + 1] + eb2b;
            float2 kv = *(const float2*)(Krow + t2);
            float2 qv = *(const float2*)(Qrow + t2);
            float p0 = s1a * s2a, p1 = s1b * s2b;
            float sc0 = copysignf(sqrt_approx(fabsf(p0)), p0) + kv.x + qv.x;
            float sc1 = copysignf(sqrt_approx(fabsf(p1)), p1) + kv.y + qv.y;
            *(float2*)(oEp + t2) = make_float2(sc0, sc1);
            a += sc0 * aw0 + sc1 * aw1;
        }
        {
            float s1a = acc[m][1][qh * 2]     + eb1c;
            float s1b = acc[m][1][qh * 2 + 1] + eb1d;
            float s2a = acc[m][3][qh * 2]     + eb2c;
            float s2b = acc[m][3][qh * 2 + 1] + eb2d;
            float2 kv = *(const float2*)(Krow + 8 + t2);
            float2 qv = *(const float2*)(Qrow + 8 + t2);
            float p0 = s1a * s2a, p1 = s1b * s2b;
            float sc0 = copysignf(sqrt_approx(fabsf(p0)), p0) + kv.x + qv.x;
            float sc1 = copysignf(sqrt_approx(fabsf(p1)), p1) + kv.y + qv.y;
            *(float2*)(oEp + 8 + t2) = make_float2(sc0, sc1);
            a += sc0 * aw8 + sc1 * aw9;
        }
        apart[r] = a;
    }

    #pragma unroll
    for (int r = 0; r < 4; r++) {
        apart[r] += __shfl_xor_sync(0xffffffffu, apart[r], 1);
        apart[r] += __shfl_xor_sync(0xffffffffu, apart[r], 2);
    }
    if ((l & 3) == 0) {
        #pragma unroll
        for (int r = 0; r < 4; r++) {
            const int e = m0 + rg * 32 + (r >> 1) * 16 + g + (r & 1) * 8;
            float a = fminf(fmaxf(apart[r], -5.0f), 5.0f);
            g_w[(size_t)e * 8 + h] = expf(a);
        }
    }
}

// ---------------- K3: CSR build ---------------------------------------------
__global__ void zero_kernel()
{
    int i = blockIdx.x * blockDim.x + threadIdx.x;
    if (i < NNODES) g_deg[i] = 0;
}
__global__ void hist_kernel(const int* __restrict__ eidx)
{
    int e = blockIdx.x * blockDim.x + threadIdx.x;
    if (e < NEDGES) atomicAdd(&g_deg[eidx[NEDGES + e]], 1);
}
__global__ __launch_bounds__(SCAN_BLK) void scan1_kernel()
{
    __shared__ int warpsum[SCAN_BLK / 32];
    const int b = blockIdx.x, t = threadIdx.x;
    const int i = b * SCAN_BLK + t;
    int v = (i < NNODES) ? g_deg[i] : 0;
    int s = v;
    #pragma unroll
    for (int o = 1; o < 32; o <<= 1) {
        int u = __shfl_up_sync(0xffffffffu, s, o);
        if ((t & 31) >= o) s += u;
    }
    if ((t & 31) == 31) warpsum[t >> 5] = s;
    __syncthreads();
    if (t < SCAN_BLK / 32) {
        int ws = warpsum[t];
        #pragma unroll
        for (int o = 1; o < SCAN_BLK / 32; o <<= 1) {
            int u = __shfl_up_sync((1u << (SCAN_BLK / 32)) - 1u, ws, o);
            if (t >= o) ws += u;
        }
        warpsum[t] = ws;
    }
    __syncthreads();
    int excl = s - v + ((t >> 5) ? warpsum[(t >> 5) - 1] : 0);
    if (i < NNODES) g_off[i] = excl;
    if (t == SCAN_BLK - 1) g_bsum[b] = excl + v;
}
__global__ void scan2_kernel()
{
    __shared__ int ws[4];
    const int t = threadIdx.x;   // 128
    int v = (t < NSCB) ? g_bsum[t] : 0;
    int s = v;
    #pragma unroll
    for (int o = 1; o < 32; o <<= 1) {
        int u = __shfl_up_sync(0xffffffffu, s, o);
        if ((t & 31) >= o) s += u;
    }
    if ((t & 31) == 31) ws[t >> 5] = s;
    __syncthreads();
    if (t < 4) {
        int wv = ws[t];
        #pragma unroll
        for (int o = 1; o < 4; o <<= 1) {
            int u = __shfl_up_sync(0xfu, wv, o);
            if (t >= o) wv += u;
        }
        ws[t] = wv;
    }
    __syncthreads();
    int excl = s - v + ((t >> 5) ? ws[(t >> 5) - 1] : 0);
    if (t < NSCB) g_bpre[t] = excl;
    if (t == NSCB - 1) g_off[NNODES] = excl + v;
}
__global__ void scan3_kernel()
{
    int i = blockIdx.x * blockDim.x + threadIdx.x;
    if (i < NNODES) {
        int o = g_off[i] + g_bpre[i >> 8];
        g_off[i] = o;
        g_cursor[i] = o;
    }
}
__global__ void scatter_kernel(const int* __restrict__ eidx)
{
    int e = blockIdx.x * blockDim.x + threadIdx.x;
    if (e < NEDGES) {
        int dst = eidx[NEDGES + e];
        int p = atomicAdd(&g_cursor[dst], 1);
        g_csr[p] = make_int2(e, eidx[e]);
    }
}

// ---------------- K4: fused softmax + aggregation (2-way edge-parallel) -----
// 256 threads/node: two 128-thread groups stride the edge list; partials
// combined in smem. csr loads are warp-uniform (hardware broadcast).
__global__ __launch_bounds__(256) void node_kernel(
    const float* __restrict__ VeRow,
    const float* __restrict__ oE,
    float* __restrict__ n_out)
{
    __shared__ float sV[128], sR[128], sD[128];
    __shared__ float rowS[8][17];
    const int n  = blockIdx.x;
    const int t  = threadIdx.x;
    const int p  = t >> 7;          // group 0/1
    const int tl = t & 127;
    const int h  = tl >> 4, c = tl & 15;
    const int beg = g_off[n], end = g_off[n + 1];

    float den = 0.f, accV = 0.f, accR = 0.f;
    for (int i = beg + p; i < end; i += 2) {
        int2 pr = g_csr[i];                         // warp-uniform: broadcast
        float wv = g_w[(size_t)pr.x * 8 + h];
        den  += wv;
        accV += wv * g_V[(size_t)pr.y * HD + tl];
        accR += wv * oE[(size_t)pr.x * HD + tl];
    }
    if (p) { sV[tl] = accV; sR[tl] = accR; sD[tl] = den; }
    __syncthreads();

    float inv = 0.f;
    if (p == 0) {
        accV += sV[tl]; accR += sR[tl]; den += sD[tl];
        inv = 1.f / (den + 1e-16f);
        rowS[h][c] = accR * inv;
    }
    __syncthreads();

    if (p == 0) {
        float r = 0.f;
        #pragma unroll
        for (int d = 0; d < 16; d++)
            r += rowS[h][d] * VeRow[d * HD + h * 16 + c];
        n_out[(size_t)n * HD + tl] = accV * inv + r;
    }
}

// ---------------- launch -----------------------------------------------------
extern "C" void kernel_launch(void* const* d_in, const int* in_sizes, int n_in,
                              void* d_out, int out_size)
{
    const float* x     = (const float*)d_in[0];
    const float* eattr = (const float*)d_in[1];
    const int*   eidx  = (const int*)  d_in[2];
    const float* Qw = (const float*)d_in[3];  const float* Qb = (const float*)d_in[4];
    const float* Kw = (const float*)d_in[5];  const float* Kb = (const float*)d_in[6];
    const float* Ew = (const float*)d_in[7];  const float* Eb = (const float*)d_in[8];
    const float* Vw = (const float*)d_in[9];  const float* Vb = (const float*)d_in[10];
    const float* Aw = (const float*)d_in[11]; const float* VeRow = (const float*)d_in[12];
    float* out = (float*)d_out;

    cudaFuncSetAttribute(edge_kernel, cudaFuncAttributeMaxDynamicSharedMemorySize,
                         SMEM_EDGE_TOTAL);
    cudaFuncSetAttribute(qkv_kernel, cudaFuncAttributeMaxDynamicSharedMemorySize,
                         SMEM_QKV_TOTAL);

    cudaStream_t s = 0;
    cudaStream_t sideS;
    cudaEvent_t  evFork, evW, evJoin;
    cudaStreamCreateWithFlags(&sideS, cudaStreamNonBlocking);
    cudaEventCreateWithFlags(&evFork, cudaEventDisableTiming);
    cudaEventCreateWithFlags(&evW,    cudaEventDisableTiming);
    cudaEventCreateWithFlags(&evJoin, cudaEventDisableTiming);

    cudaEventRecord(evFork, s);
    cudaStreamWaitEvent(sideS, evFork, 0);

    // main: weight prep + Q,K GEMMs
    bprep_kernel<<<4, 256, 0, s>>>(Ew);
    wprep_kernel<<<3, 256, 0, s>>>(Qw, Kw, Vw);
    cudaEventRecord(evW, s);
    qkv_kernel<<<dim3((NNODES + 127) / 128, 2), 512, SMEM_QKV_TOTAL, s>>>(
        x, Qb, Kb, Vb, 0);                                      // Q, K

    // side: CSR build, then V GEMM (after wprep)
    zero_kernel<<<(NNODES + 255) / 256, 256, 0, sideS>>>();
    hist_kernel<<<(NEDGES + 255) / 256, 256, 0, sideS>>>(eidx);
    scan1_kernel<<<NSCB, SCAN_BLK, 0, sideS>>>();
    scan2_kernel<<<1, 128, 0, sideS>>>();
    scan3_kernel<<<(NNODES + 255) / 256, 256, 0, sideS>>>();
    scatter_kernel<<<(NEDGES + 255) / 256, 256, 0, sideS>>>(eidx);
    cudaStreamWaitEvent(sideS, evW, 0);
    qkv_kernel<<<dim3((NNODES + 127) / 128, 1), 512, SMEM_QKV_TOTAL, sideS>>>(
        x, Qb, Kb, Vb, 2);                                      // V
    cudaEventRecord(evJoin, sideS);

    // main: edge GEMM (needs Q,K), then node (needs V + CSR + oE/g_w)
    edge_kernel<<<NEDGES / 128, 1024, SMEM_EDGE_TOTAL, s>>>(eattr, eidx, Eb, Aw, out);
    cudaStreamWaitEvent(s, evJoin, 0);
    node_kernel<<<NNODES, 256, 0, s>>>(VeRow, out + OUT_OE, out);
}

// round 16
// speedup vs baseline: 1.1093x; 1.1093x over previous
#include <cuda_runtime.h>
#include <cuda_bf16.h>
#include <math.h>
#include <stdint.h>

#define NNODES 20000
#define NEDGES 320000
#define HD 128
#define OUT_OE (NNODES * HD)

// ---------------- scratch ----------------------------------------------------
__device__ float g_Q[NNODES * HD];
__device__ float g_K[NNODES * HD];
__device__ float g_V[NNODES * HD];
__device__ float g_w[NEDGES * 8];
__device__ int   g_deg[NNODES];
__device__ int   g_off[NNODES + 1];
__device__ int   g_cursor[NNODES];
__device__ int2  g_csr[NEDGES];
#define SCAN_BLK 256
#define NSCB ((NNODES + SCAN_BLK - 1) / SCAN_BLK)
__device__ int   g_bsum[NSCB];
__device__ int   g_bpre[NSCB];
// pre-swizzled bf16 images
__device__ unsigned long long g_Bh[4096];        // Ew hi: [64 k][256 n], 32KB
__device__ unsigned long long g_Bl[4096];        // Ew lo
__device__ unsigned long long g_Wh[3 * 2048];    // Qw/Kw/Vw hi
__device__ unsigned long long g_Wl[3 * 2048];    // Qw/Kw/Vw lo

// ---------------- helpers ----------------------------------------------------
__device__ __forceinline__ uint32_t smem_u32(const void* p) {
    uint32_t a;
    asm("{ .reg .u64 t; cvta.to.shared.u64 t, %1; cvt.u32.u64 %0, t; }" : "=r"(a) : "l"(p));
    return a;
}
__device__ __forceinline__ unsigned long long pack4_hi(float4 v) {
    unsigned short h0 = __bfloat16_as_ushort(__float2bfloat16(v.x));
    unsigned short h1 = __bfloat16_as_ushort(__float2bfloat16(v.y));
    unsigned short h2 = __bfloat16_as_ushort(__float2bfloat16(v.z));
    unsigned short h3 = __bfloat16_as_ushort(__float2bfloat16(v.w));
    return (unsigned long long)h0 | ((unsigned long long)h1 << 16) |
           ((unsigned long long)h2 << 32) | ((unsigned long long)h3 << 48);
}
__device__ __forceinline__ float4 resid4(float4 v) {
    return make_float4(
        v.x - __bfloat162float(__float2bfloat16(v.x)),
        v.y - __bfloat162float(__float2bfloat16(v.y)),
        v.z - __bfloat162float(__float2bfloat16(v.z)),
        v.w - __bfloat162float(__float2bfloat16(v.w)));
}
__device__ __forceinline__ void ldmatrix_x4(uint32_t* r, uint32_t addr) {
    asm volatile("ldmatrix.sync.aligned.m8n8.x4.shared.b16 {%0,%1,%2,%3}, [%4];"
                 : "=r"(r[0]), "=r"(r[1]), "=r"(r[2]), "=r"(r[3]) : "r"(addr));
}
__device__ __forceinline__ void ldmatrix_x4t(uint32_t* r, uint32_t addr) {
    asm volatile("ldmatrix.sync.aligned.m8n8.x4.trans.shared.b16 {%0,%1,%2,%3}, [%4];"
                 : "=r"(r[0]), "=r"(r[1]), "=r"(r[2]), "=r"(r[3]) : "r"(addr));
}
__device__ __forceinline__ void mma16816(float* c, const uint32_t* a, const uint32_t* b) {
    asm volatile(
        "mma.sync.aligned.m16n8k16.row.col.f32.bf16.bf16.f32 "
        "{%0,%1,%2,%3}, {%4,%5,%6,%7}, {%8,%9}, {%0,%1,%2,%3};"
        : "+f"(c[0]), "+f"(c[1]), "+f"(c[2]), "+f"(c[3])
        : "r"(a[0]), "r"(a[1]), "r"(a[2]), "r"(a[3]), "r"(b[0]), "r"(b[1]));
}
__device__ __forceinline__ float sqrt_approx(float x) {
    float r;
    asm("sqrt.approx.f32 %0, %1;" : "=f"(r) : "f"(x));
    return r;
}

// ---------------- K0a: Ew -> bf16 hi/lo pre-swizzled image [64][256] --------
__global__ void bprep_kernel(const float* __restrict__ Ew)
{
    const int jb = blockIdx.x;    // 0..3
    const int t  = threadIdx.x;   // 256
    #pragma unroll
    for (int it = 0; it < 4; it++) {
        int idx = it * 256 + t;
        int k   = idx >> 4;
        int n4l = (idx & 15) * 4;
        int n   = jb * 64 + n4l;
        const float* p = Ew + (size_t)k * 256 + n;
        float4 v = make_float4(p[0], p[1], p[2], p[3]);
        unsigned int byte = (unsigned)k * 512 + (((unsigned)n * 2) ^ (((unsigned)k & 7) << 4));
        g_Bh[byte >> 3] = pack4_hi(v);
        g_Bl[byte >> 3] = pack4_hi(resid4(v));
    }
}

// ---------------- K0b: Qw/Kw/Vw -> bf16 hi/lo images [64][128] each ---------
__global__ void wprep_kernel(const float* __restrict__ Qw,
                             const float* __restrict__ Kw,
                             const float* __restrict__ Vw)
{
    const int sel = blockIdx.x;   // 0..2
    const float* W = (sel == 0) ? Qw : ((sel == 1) ? Kw : Vw);
    const int t = threadIdx.x;    // 256
    #pragma unroll
    for (int it = 0; it < 8; it++) {
        int idx = it * 256 + t;
        int k   = idx >> 5;
        int n4  = (idx & 31) * 4;
        const float* p = W + (size_t)k * 128 + n4;
        float4 v = make_float4(p[0], p[1], p[2], p[3]);
        unsigned int byte = (unsigned)k * 256 + (((unsigned)n4 * 2) ^ (((unsigned)k & 7) << 4));
        unsigned int i8 = ((unsigned)sel * 16384 + byte) >> 3;
        g_Wh[i8] = pack4_hi(v);
        g_Wl[i8] = pack4_hi(resid4(v));
    }
}

// ---------------- K1: QKV node GEMM via mma.sync bf16 hi/lo (3-term) --------
// selofs: 0 -> blockIdx.y in {0,1} = Q,K (main stream); 2 -> V (side stream)
#define QSM_A_HI 0
#define QSM_A_LO 16384
#define QSM_B_HI 32768
#define QSM_B_LO 49152
#define SMEM_QKV_TOTAL 65536

__global__ __launch_bounds__(512, 2) void qkv_kernel(
    const float* __restrict__ x,
    const float* __restrict__ Qb, const float* __restrict__ Kb,
    const float* __restrict__ Vb, int selofs)
{
    extern __shared__ char smem[];
    const uint32_t sbase = smem_u32(smem);
    const int t   = threadIdx.x;
    const int l   = t & 31;
    const int w   = t >> 5;
    const int m0  = blockIdx.x * 128;
    const int sel = blockIdx.y + selofs;
    const float* Bv = (sel == 0) ? Qb : ((sel == 1) ? Kb : Vb);
    float* out      = (sel == 0) ? g_Q : ((sel == 1) ? g_K : g_V);

    #pragma unroll
    for (int it = 0; it < 4; it++) {
        int idx = it * 512 + t;
        int row = idx >> 4;
        int c4  = (idx & 15) * 4;
        float4 v = make_float4(0.f, 0.f, 0.f, 0.f);
        if (m0 + row < NNODES) v = *(const float4*)(x + (size_t)(m0 + row) * 64 + c4);
        unsigned int byte = (unsigned)row * 128 + (((unsigned)c4 * 2) ^ (((unsigned)row & 7) << 4));
        *(unsigned long long*)(smem + QSM_A_HI + byte) = pack4_hi(v);
        *(unsigned long long*)(smem + QSM_A_LO + byte) = pack4_hi(resid4(v));
    }
    {
        const ulonglong2* bh = (const ulonglong2*)(g_Wh + sel * 2048);
        const ulonglong2* bl = (const ulonglong2*)(g_Wl + sel * 2048);
        ulonglong2* dh = (ulonglong2*)(smem + QSM_B_HI);
        ulonglong2* dl = (ulonglong2*)(smem + QSM_B_LO);
        #pragma unroll
        for (int it = 0; it < 2; it++) {
            int idx = it * 512 + t;
            dh[idx] = bh[idx];
            dl[idx] = bl[idx];
        }
    }
    __syncthreads();

    const int rg   = w >> 2;
    const int cg   = w & 3;
    const int g    = l >> 2;
    const int t2   = (l & 3) * 2;
    const int lx   = l & 7;
    const int bl15 = l & 15;
    const int jhi  = l >> 4;
    const int arow = rg * 32 + (l & 15);
    const int asw  = ((l & 15) & 7) << 4;

    float acc[2][4][4];
    #pragma unroll
    for (int m = 0; m < 2; m++)
        #pragma unroll
        for (int n = 0; n < 4; n++)
            #pragma unroll
            for (int q = 0; q < 4; q++) acc[m][n][q] = 0.f;

    #pragma unroll
    for (int ks = 0; ks < 4; ks++) {
        uint32_t ah[2][4], al[2][4];
        #pragma unroll
        for (int m = 0; m < 2; m++) {
            uint32_t aoff = (unsigned)(arow + m * 16) * 128 +
                            (((unsigned)(32 * ks + (l & 16))) ^ (unsigned)asw);
            ldmatrix_x4(ah[m], sbase + QSM_A_HI + aoff);
            ldmatrix_x4(al[m], sbase + QSM_A_LO + aoff);
        }
        uint32_t browoff = (unsigned)(16 * ks + bl15) * 256;
        #pragma unroll
        for (int np = 0; np < 2; np++) {
            uint32_t boff = ((unsigned)((cg * 4 + np * 2 + jhi) ^ lx)) << 4;
            uint32_t bh[4], blo[4];
            ldmatrix_x4t(bh,  sbase + QSM_B_HI + browoff + boff);
            ldmatrix_x4t(blo, sbase + QSM_B_LO + browoff + boff);
            #pragma unroll
            for (int m = 0; m < 2; m++) {
                mma16816(acc[m][np * 2],     ah[m], bh);
                mma16816(acc[m][np * 2 + 1], ah[m], bh + 2);
                mma16816(acc[m][np * 2],     al[m], bh);
                mma16816(acc[m][np * 2 + 1], al[m], bh + 2);
                mma16816(acc[m][np * 2],     ah[m], blo);
                mma16816(acc[m][np * 2 + 1], ah[m], blo + 2);
            }
        }
    }

    float2 bias[4];
    #pragma unroll
    for (int n = 0; n < 4; n++) {
        int col = cg * 32 + n * 8 + t2;
        bias[n] = make_float2(__ldg(Bv + col), __ldg(Bv + col + 1));
    }
    #pragma unroll
    for (int m = 0; m < 2; m++) {
        int row0 = m0 + rg * 32 + m * 16 + g;
        #pragma unroll
        for (int n = 0; n < 4; n++) {
            int col = cg * 32 + n * 8 + t2;
            if (row0 < NNODES)
                *(float2*)(out + (size_t)row0 * HD + col) =
                    make_float2(acc[m][n][0] + bias[n].x, acc[m][n][1] + bias[n].y);
            if (row0 + 8 < NNODES)
                *(float2*)(out + (size_t)(row0 + 8) * HD + col) =
                    make_float2(acc[m][n][2] + bias[n].x, acc[m][n][3] + bias[n].y);
        }
    }
}

// ---------------- K2: edge GEMM, BN=256 (all 8 heads), reg epilogue ---------
// 1024 threads / 32 warps; warp = 32 rows x 1 head. 3-term hi/lo split.
#define SM_A_HI 0
#define SM_A_LO 16384
#define SM_B_HI 32768
#define SM_B_LO 65536
#define SMEM_EDGE_TOTAL 98304

__global__ __launch_bounds__(1024, 1) void edge_kernel(
    const float* __restrict__ eattr, const int* __restrict__ eidx,
    const float* __restrict__ Eb, const float* __restrict__ Aw,
    float* __restrict__ outbuf)
{
    extern __shared__ char smem[];
    const uint32_t sbase = smem_u32(smem);
    const int t   = threadIdx.x;
    const int l   = t & 31;
    const int w   = t >> 5;
    const int m0  = blockIdx.x * 128;

    // ---- A tile: 128 edges x 64 K -> hi/lo bf16, swizzled (128B rows)
    #pragma unroll
    for (int it = 0; it < 2; it++) {
        int idx = it * 1024 + t;
        int row = idx >> 4;
        int c4  = (idx & 15) * 4;
        float4 v = __ldcs((const float4*)(eattr + (size_t)(m0 + row) * 64 + c4));
        unsigned int byte = (unsigned)row * 128 + (((unsigned)c4 * 2) ^ (((unsigned)row & 7) << 4));
        *(unsigned long long*)(smem + SM_A_HI + byte) = pack4_hi(v);
        *(unsigned long long*)(smem + SM_A_LO + byte) = pack4_hi(resid4(v));
    }
    // ---- B image copy (32KB each)
    {
        const ulonglong2* bh = (const ulonglong2*)g_Bh;
        const ulonglong2* bl = (const ulonglong2*)g_Bl;
        ulonglong2* dh = (ulonglong2*)(smem + SM_B_HI);
        ulonglong2* dl = (ulonglong2*)(smem + SM_B_LO);
        #pragma unroll
        for (int it = 0; it < 2; it++) {
            int idx = it * 1024 + t;
            dh[idx] = bh[idx];
            dl[idx] = bl[idx];
        }
    }
    __syncthreads();

    // ---- MMA: warp w -> rows 32*(w>>3)..+31, head (w&7)
    const int rg   = w >> 3;
    const int cg   = w & 7;
    const int g    = l >> 2;
    const int t2   = (l & 3) * 2;
    const int lx   = l & 7;
    const int bl15 = l & 15;
    const int jhi  = l >> 4;
    const int arow = rg * 32 + (l & 15);
    const int asw  = ((l & 15) & 7) << 4;

    float acc[2][4][4];
    #pragma unroll
    for (int m = 0; m < 2; m++)
        #pragma unroll
        for (int n = 0; n < 4; n++)
            #pragma unroll
            for (int q = 0; q < 4; q++) acc[m][n][q] = 0.f;

    #pragma unroll
    for (int ks = 0; ks < 4; ks++) {
        uint32_t ah[2][4], al[2][4];
        #pragma unroll
        for (int m = 0; m < 2; m++) {
            uint32_t aoff = (unsigned)(arow + m * 16) * 128 +
                            (((unsigned)(32 * ks + (l & 16))) ^ (unsigned)asw);
            ldmatrix_x4(ah[m], sbase + SM_A_HI + aoff);
            ldmatrix_x4(al[m], sbase + SM_A_LO + aoff);
        }
        uint32_t browoff = (unsigned)(16 * ks + bl15) * 512;   // 512B rows (256 cols)
        #pragma unroll
        for (int np = 0; np < 2; np++) {
            uint32_t boff = ((unsigned)((cg * 4 + np * 2 + jhi) ^ lx)) << 4;
            uint32_t bh[4], blo[4];
            ldmatrix_x4t(bh,  sbase + SM_B_HI + browoff + boff);
            ldmatrix_x4t(blo, sbase + SM_B_LO + browoff + boff);
            #pragma unroll
            for (int m = 0; m < 2; m++) {
                mma16816(acc[m][np * 2],     ah[m], bh);
                mma16816(acc[m][np * 2 + 1], ah[m], bh + 2);
                mma16816(acc[m][np * 2],     al[m], bh);
                mma16816(acc[m][np * 2 + 1], al[m], bh + 2);
                mma16816(acc[m][np * 2],     ah[m], blo);
                mma16816(acc[m][np * 2 + 1], ah[m], blo + 2);
            }
        }
    }

    // ---- epilogue (in registers) ----
    const int h    = cg;
    const int colK = h * 16;

    // hoist index loads (better MLP over the gather latency)
    int srcs[4], dsts[4];
    #pragma unroll
    for (int r = 0; r < 4; r++) {
        const int e = m0 + rg * 32 + (r >> 1) * 16 + g + (r & 1) * 8;
        srcs[r] = eidx[e];
        dsts[r] = eidx[NEDGES + e];
    }

    const float eb1a = __ldg(Eb + h * 32 + t2);
    const float eb1b = __ldg(Eb + h * 32 + t2 + 1);
    const float eb1c = __ldg(Eb + h * 32 + 8 + t2);
    const float eb1d = __ldg(Eb + h * 32 + 8 + t2 + 1);
    const float eb2a = __ldg(Eb + h * 32 + 16 + t2);
    const float eb2b = __ldg(Eb + h * 32 + 16 + t2 + 1);
    const float eb2c = __ldg(Eb + h * 32 + 24 + t2);
    const float eb2d = __ldg(Eb + h * 32 + 24 + t2 + 1);
    const float aw0 = __ldg(Aw + (t2)     * 8 + h);
    const float aw1 = __ldg(Aw + (t2 + 1) * 8 + h);
    const float aw8 = __ldg(Aw + (8 + t2)     * 8 + h);
    const float aw9 = __ldg(Aw + (8 + t2 + 1) * 8 + h);

    float apart[4];
    #pragma unroll
    for (int r = 0; r < 4; r++) {
        const int m  = r >> 1;
        const int qh = r & 1;
        const int e  = m0 + rg * 32 + m * 16 + g + qh * 8;
        const float* Krow = g_K + (size_t)srcs[r] * HD + colK;
        const float* Qrow = g_Q + (size_t)dsts[r] * HD + colK;
        float* oEp = outbuf + (size_t)OUT_OE + (size_t)e * HD + colK;

        float a = 0.f;
        {
            float s1a = acc[m][0][qh * 2]     + eb1a;
            float s1b = acc[m][0][qh * 2 + 1] + eb1b;
            float s2a = acc[m][2][qh * 2]     + eb2a;
            float s2b = acc[m][2][qh * 2 + 1] + eb2b;
            float2 kv = *(const float2*)(Krow + t2);
            float2 qv = *(const float2*)(Qrow + t2);
            float p0 = s1a * s2a, p1 = s1b * s2b;
            float sc0 = copysignf(sqrt_approx(fabsf(p0)), p0) + kv.x + qv.x;
            float sc1 = copysignf(sqrt_approx(fabsf(p1)), p1) + kv.y + qv.y;
            __stcs((float2*)(oEp + t2), make_float2(sc0, sc1));
            a += sc0 * aw0 + sc1 * aw1;
        }
        {
            float s1a = acc[m][1][qh * 2]     + eb1c;
            float s1b = acc[m][1][qh * 2 + 1] + eb1d;
            float s2a = acc[m][3][qh * 2]     + eb2c;
            float s2b = acc[m][3][qh * 2 + 1] + eb2d;
            float2 kv = *(const float2*)(Krow + 8 + t2);
            float2 qv = *(const float2*)(Qrow + 8 + t2);
            float p0 = s1a * s2a, p1 = s1b * s2b;
            float sc0 = copysignf(sqrt_approx(fabsf(p0)), p0) + kv.x + qv.x;
            float sc1 = copysignf(sqrt_approx(fabsf(p1)), p1) + kv.y + qv.y;
            __stcs((float2*)(oEp + 8 + t2), make_float2(sc0, sc1));
            a += sc0 * aw8 + sc1 * aw9;
        }
        apart[r] = a;
    }

    #pragma unroll
    for (int r = 0; r < 4; r++) {
        apart[r] += __shfl_xor_sync(0xffffffffu, apart[r], 1);
        apart[r] += __shfl_xor_sync(0xffffffffu, apart[r], 2);
    }
    if ((l & 3) == 0) {
        #pragma unroll
        for (int r = 0; r < 4; r++) {
            const int e = m0 + rg * 32 + (r >> 1) * 16 + g + (r & 1) * 8;
            float a = fminf(fmaxf(apart[r], -5.0f), 5.0f);
            g_w[(size_t)e * 8 + h] = expf(a);
        }
    }
}

// ---------------- K3: CSR build ---------------------------------------------
__global__ void zero_kernel()
{
    int i = blockIdx.x * blockDim.x + threadIdx.x;
    if (i < NNODES) g_deg[i] = 0;
}
__global__ void hist_kernel(const int* __restrict__ eidx)
{
    int e = blockIdx.x * blockDim.x + threadIdx.x;
    if (e < NEDGES) atomicAdd(&g_deg[eidx[NEDGES + e]], 1);
}
__global__ __launch_bounds__(SCAN_BLK) void scan1_kernel()
{
    __shared__ int warpsum[SCAN_BLK / 32];
    const int b = blockIdx.x, t = threadIdx.x;
    const int i = b * SCAN_BLK + t;
    int v = (i < NNODES) ? g_deg[i] : 0;
    int s = v;
    #pragma unroll
    for (int o = 1; o < 32; o <<= 1) {
        int u = __shfl_up_sync(0xffffffffu, s, o);
        if ((t & 31) >= o) s += u;
    }
    if ((t & 31) == 31) warpsum[t >> 5] = s;
    __syncthreads();
    if (t < SCAN_BLK / 32) {
        int ws = warpsum[t];
        #pragma unroll
        for (int o = 1; o < SCAN_BLK / 32; o <<= 1) {
            int u = __shfl_up_sync((1u << (SCAN_BLK / 32)) - 1u, ws, o);
            if (t >= o) ws += u;
        }
        warpsum[t] = ws;
    }
    __syncthreads();
    int excl = s - v + ((t >> 5) ? warpsum[(t >> 5) - 1] : 0);
    if (i < NNODES) g_off[i] = excl;
    if (t == SCAN_BLK - 1) g_bsum[b] = excl + v;
}
__global__ void scan2_kernel()
{
    __shared__ int ws[4];
    const int t = threadIdx.x;   // 128
    int v = (t < NSCB) ? g_bsum[t] : 0;
    int s = v;
    #pragma unroll
    for (int o = 1; o < 32; o <<= 1) {
        int u = __shfl_up_sync(0xffffffffu, s, o);
        if ((t & 31) >= o) s += u;
    }
    if ((t & 31) == 31) ws[t >> 5] = s;
    __syncthreads();
    if (t < 4) {
        int wv = ws[t];
        #pragma unroll
        for (int o = 1; o < 4; o <<= 1) {
            int u = __shfl_up_sync(0xfu, wv, o);
            if (t >= o) wv += u;
        }
        ws[t] = wv;
    }
    __syncthreads();
    int excl = s - v + ((t >> 5) ? ws[(t >> 5) - 1] : 0);
    if (t < NSCB) g_bpre[t] = excl;
    if (t == NSCB - 1) g_off[NNODES] = excl + v;
}
__global__ void scan3_kernel()
{
    int i = blockIdx.x * blockDim.x + threadIdx.x;
    if (i < NNODES) {
        int o = g_off[i] + g_bpre[i >> 8];
        g_off[i] = o;
        g_cursor[i] = o;
    }
}
__global__ void scatter_kernel(const int* __restrict__ eidx)
{
    int e = blockIdx.x * blockDim.x + threadIdx.x;
    if (e < NEDGES) {
        int dst = eidx[NEDGES + e];
        int p = atomicAdd(&g_cursor[dst], 1);
        g_csr[p] = make_int2(e, eidx[e]);
    }
}

// ---------------- K4: fused softmax + aggregation (R14 version) -------------
__global__ __launch_bounds__(128) void node_kernel(
    const float* __restrict__ VeRow,
    const float* __restrict__ oE,
    float* __restrict__ n_out)
{
    __shared__ int2  stage[128];
    __shared__ float rowS[8][17];
    const int n = blockIdx.x;
    const int t = threadIdx.x;
    const int h = t >> 4, c = t & 15;
    const int beg = g_off[n], end = g_off[n + 1];

    float den = 0.f, accV = 0.f, accR = 0.f;
    for (int base = beg; base < end; base += 128) {
        int cnt = min(128, end - base);
        __syncthreads();
        if (t < cnt) stage[t] = g_csr[base + t];
        __syncthreads();
        #pragma unroll 4
        for (int i = 0; i < cnt; i++) {
            int e   = stage[i].x;
            int src = stage[i].y;
            float wv = g_w[(size_t)e * 8 + h];
            den  += wv;
            accV += wv * g_V[(size_t)src * HD + t];
            accR += wv * __ldcs(oE + (size_t)e * HD + t);
        }
    }
    float inv = 1.f / (den + 1e-16f);

    rowS[h][c] = accR * inv;
    __syncthreads();
    float r = 0.f;
    #pragma unroll
    for (int d = 0; d < 16; d++)
        r += rowS[h][d] * VeRow[d * HD + h * 16 + c];

    n_out[(size_t)n * HD + t] = accV * inv + r;
}

// ---------------- launch -----------------------------------------------------
extern "C" void kernel_launch(void* const* d_in, const int* in_sizes, int n_in,
                              void* d_out, int out_size)
{
    const float* x     = (const float*)d_in[0];
    const float* eattr = (const float*)d_in[1];
    const int*   eidx  = (const int*)  d_in[2];
    const float* Qw = (const float*)d_in[3];  const float* Qb = (const float*)d_in[4];
    const float* Kw = (const float*)d_in[5];  const float* Kb = (const float*)d_in[6];
    const float* Ew = (const float*)d_in[7];  const float* Eb = (const float*)d_in[8];
    const float* Vw = (const float*)d_in[9];  const float* Vb = (const float*)d_in[10];
    const float* Aw = (const float*)d_in[11]; const float* VeRow = (const float*)d_in[12];
    float* out = (float*)d_out;

    cudaFuncSetAttribute(edge_kernel, cudaFuncAttributeMaxDynamicSharedMemorySize,
                         SMEM_EDGE_TOTAL);
    cudaFuncSetAttribute(qkv_kernel, cudaFuncAttributeMaxDynamicSharedMemorySize,
                         SMEM_QKV_TOTAL);

    cudaStream_t s = 0;
    cudaStream_t sideS;
    cudaEvent_t  evFork, evW, evB, evJoin;
    cudaStreamCreateWithFlags(&sideS, cudaStreamNonBlocking);
    cudaEventCreateWithFlags(&evFork, cudaEventDisableTiming);
    cudaEventCreateWithFlags(&evW,    cudaEventDisableTiming);
    cudaEventCreateWithFlags(&evB,    cudaEventDisableTiming);
    cudaEventCreateWithFlags(&evJoin, cudaEventDisableTiming);

    cudaEventRecord(evFork, s);
    cudaStreamWaitEvent(sideS, evFork, 0);

    // side: Ew image prep first (edge needs it; done long before qkv finishes),
    // then CSR build, then V GEMM (after wprep)
    bprep_kernel<<<4, 256, 0, sideS>>>(Ew);
    cudaEventRecord(evB, sideS);
    zero_kernel<<<(NNODES + 255) / 256, 256, 0, sideS>>>();
    hist_kernel<<<(NEDGES + 255) / 256, 256, 0, sideS>>>(eidx);
    scan1_kernel<<<NSCB, SCAN_BLK, 0, sideS>>>();
    scan2_kernel<<<1, 128, 0, sideS>>>();
    scan3_kernel<<<(NNODES + 255) / 256, 256, 0, sideS>>>();
    scatter_kernel<<<(NEDGES + 255) / 256, 256, 0, sideS>>>(eidx);

    // main: weight prep + Q,K GEMMs
    wprep_kernel<<<3, 256, 0, s>>>(Qw, Kw, Vw);
    cudaEventRecord(evW, s);
    qkv_kernel<<<dim3((NNODES + 127) / 128, 2), 512, SMEM_QKV_TOTAL, s>>>(
        x, Qb, Kb, Vb, 0);                                      // Q, K

    // side: V GEMM after wprep
    cudaStreamWaitEvent(sideS, evW, 0);
    qkv_kernel<<<dim3((NNODES + 127) / 128, 1), 512, SMEM_QKV_TOTAL, sideS>>>(
        x, Qb, Kb, Vb, 2);                                      // V
    cudaEventRecord(evJoin, sideS);

    // main: edge GEMM (needs Q,K + Ew image), then node
    cudaStreamWaitEvent(s, evB, 0);
    edge_kernel<<<NEDGES / 128, 1024, SMEM_EDGE_TOTAL, s>>>(eattr, eidx, Eb, Aw, out);
    cudaStreamWaitEvent(s, evJoin, 0);
    node_kernel<<<NNODES, 128, 0, s>>>(VeRow, out + OUT_OE, out);
}

// round 17
// speedup vs baseline: 1.1462x; 1.0332x over previous
#include <cuda_runtime.h>
#include <cuda_bf16.h>
#include <math.h>
#include <stdint.h>

#define NNODES 20000
#define NEDGES 320000
#define HD 128
#define OUT_OE (NNODES * HD)

// ---------------- scratch ----------------------------------------------------
__device__ float g_Q[NNODES * HD];
__device__ float g_K[NNODES * HD];
__device__ float g_V[NNODES * HD];
__device__ float g_w[NEDGES * 8];
__device__ int   g_deg[NNODES];
__device__ int   g_off[NNODES + 1];
__device__ int   g_cursor[NNODES];
__device__ int2  g_csr[NEDGES];
#define SCAN_BLK 256
#define NSCB ((NNODES + SCAN_BLK - 1) / SCAN_BLK)
__device__ int   g_bsum[NSCB];
__device__ int   g_bpre[NSCB];
// pre-swizzled bf16 images
__device__ unsigned long long g_Bh[4096];        // Ew hi: [64 k][256 n], 32KB
__device__ unsigned long long g_Bl[4096];        // Ew lo
__device__ unsigned long long g_Wh[3 * 2048];    // Qw/Kw/Vw hi
__device__ unsigned long long g_Wl[3 * 2048];    // Qw/Kw/Vw lo

// ---------------- helpers ----------------------------------------------------
__device__ __forceinline__ uint32_t smem_u32(const void* p) {
    uint32_t a;
    asm("{ .reg .u64 t; cvta.to.shared.u64 t, %1; cvt.u32.u64 %0, t; }" : "=r"(a) : "l"(p));
    return a;
}
__device__ __forceinline__ unsigned long long pack4_hi(float4 v) {
    unsigned short h0 = __bfloat16_as_ushort(__float2bfloat16(v.x));
    unsigned short h1 = __bfloat16_as_ushort(__float2bfloat16(v.y));
    unsigned short h2 = __bfloat16_as_ushort(__float2bfloat16(v.z));
    unsigned short h3 = __bfloat16_as_ushort(__float2bfloat16(v.w));
    return (unsigned long long)h0 | ((unsigned long long)h1 << 16) |
           ((unsigned long long)h2 << 32) | ((unsigned long long)h3 << 48);
}
__device__ __forceinline__ float4 resid4(float4 v) {
    return make_float4(
        v.x - __bfloat162float(__float2bfloat16(v.x)),
        v.y - __bfloat162float(__float2bfloat16(v.y)),
        v.z - __bfloat162float(__float2bfloat16(v.z)),
        v.w - __bfloat162float(__float2bfloat16(v.w)));
}
__device__ __forceinline__ void ldmatrix_x4(uint32_t* r, uint32_t addr) {
    asm volatile("ldmatrix.sync.aligned.m8n8.x4.shared.b16 {%0,%1,%2,%3}, [%4];"
                 : "=r"(r[0]), "=r"(r[1]), "=r"(r[2]), "=r"(r[3]) : "r"(addr));
}
__device__ __forceinline__ void ldmatrix_x4t(uint32_t* r, uint32_t addr) {
    asm volatile("ldmatrix.sync.aligned.m8n8.x4.trans.shared.b16 {%0,%1,%2,%3}, [%4];"
                 : "=r"(r[0]), "=r"(r[1]), "=r"(r[2]), "=r"(r[3]) : "r"(addr));
}
__device__ __forceinline__ void mma16816(float* c, const uint32_t* a, const uint32_t* b) {
    asm volatile(
        "mma.sync.aligned.m16n8k16.row.col.f32.bf16.bf16.f32 "
        "{%0,%1,%2,%3}, {%4,%5,%6,%7}, {%8,%9}, {%0,%1,%2,%3};"
        : "+f"(c[0]), "+f"(c[1]), "+f"(c[2]), "+f"(c[3])
        : "r"(a[0]), "r"(a[1]), "r"(a[2]), "r"(a[3]), "r"(b[0]), "r"(b[1]));
}
__device__ __forceinline__ float sqrt_approx(float x) {
    float r;
    asm("sqrt.approx.f32 %0, %1;" : "=f"(r) : "f"(x));
    return r;
}

// ---------------- K0a: Ew -> bf16 hi/lo pre-swizzled image [64][256] --------
__global__ void bprep_kernel(const float* __restrict__ Ew)
{
    const int jb = blockIdx.x;    // 0..3
    const int t  = threadIdx.x;   // 256
    #pragma unroll
    for (int it = 0; it < 4; it++) {
        int idx = it * 256 + t;
        int k   = idx >> 4;
        int n4l = (idx & 15) * 4;
        int n   = jb * 64 + n4l;
        const float* p = Ew + (size_t)k * 256 + n;
        float4 v = make_float4(p[0], p[1], p[2], p[3]);
        unsigned int byte = (unsigned)k * 512 + (((unsigned)n * 2) ^ (((unsigned)k & 7) << 4));
        g_Bh[byte >> 3] = pack4_hi(v);
        g_Bl[byte >> 3] = pack4_hi(resid4(v));
    }
}

// ---------------- K0b: Qw/Kw/Vw -> bf16 hi/lo images [64][128] each ---------
__global__ void wprep_kernel(const float* __restrict__ Qw,
                             const float* __restrict__ Kw,
                             const float* __restrict__ Vw)
{
    const int sel = blockIdx.x;   // 0..2
    const float* W = (sel == 0) ? Qw : ((sel == 1) ? Kw : Vw);
    const int t = threadIdx.x;    // 256
    #pragma unroll
    for (int it = 0; it < 8; it++) {
        int idx = it * 256 + t;
        int k   = idx >> 5;
        int n4  = (idx & 31) * 4;
        const float* p = W + (size_t)k * 128 + n4;
        float4 v = make_float4(p[0], p[1], p[2], p[3]);
        unsigned int byte = (unsigned)k * 256 + (((unsigned)n4 * 2) ^ (((unsigned)k & 7) << 4));
        unsigned int i8 = ((unsigned)sel * 16384 + byte) >> 3;
        g_Wh[i8] = pack4_hi(v);
        g_Wl[i8] = pack4_hi(resid4(v));
    }
}

// ---------------- K1: QKV node GEMM via mma.sync bf16 hi/lo (3-term) --------
#define QSM_A_HI 0
#define QSM_A_LO 16384
#define QSM_B_HI 32768
#define QSM_B_LO 49152
#define SMEM_QKV_TOTAL 65536

__global__ __launch_bounds__(512, 2) void qkv_kernel(
    const float* __restrict__ x,
    const float* __restrict__ Qb, const float* __restrict__ Kb,
    const float* __restrict__ Vb, int selofs)
{
    extern __shared__ char smem[];
    const uint32_t sbase = smem_u32(smem);
    const int t   = threadIdx.x;
    const int l   = t & 31;
    const int w   = t >> 5;
    const int m0  = blockIdx.x * 128;
    const int sel = blockIdx.y + selofs;
    const float* Bv = (sel == 0) ? Qb : ((sel == 1) ? Kb : Vb);
    float* out      = (sel == 0) ? g_Q : ((sel == 1) ? g_K : g_V);

    #pragma unroll
    for (int it = 0; it < 4; it++) {
        int idx = it * 512 + t;
        int row = idx >> 4;
        int c4  = (idx & 15) * 4;
        float4 v = make_float4(0.f, 0.f, 0.f, 0.f);
        if (m0 + row < NNODES) v = *(const float4*)(x + (size_t)(m0 + row) * 64 + c4);
        unsigned int byte = (unsigned)row * 128 + (((unsigned)c4 * 2) ^ (((unsigned)row & 7) << 4));
        *(unsigned long long*)(smem + QSM_A_HI + byte) = pack4_hi(v);
        *(unsigned long long*)(smem + QSM_A_LO + byte) = pack4_hi(resid4(v));
    }
    {
        const ulonglong2* bh = (const ulonglong2*)(g_Wh + sel * 2048);
        const ulonglong2* bl = (const ulonglong2*)(g_Wl + sel * 2048);
        ulonglong2* dh = (ulonglong2*)(smem + QSM_B_HI);
        ulonglong2* dl = (ulonglong2*)(smem + QSM_B_LO);
        #pragma unroll
        for (int it = 0; it < 2; it++) {
            int idx = it * 512 + t;
            dh[idx] = bh[idx];
            dl[idx] = bl[idx];
        }
    }
    __syncthreads();

    const int rg   = w >> 2;
    const int cg   = w & 3;
    const int g    = l >> 2;
    const int t2   = (l & 3) * 2;
    const int lx   = l & 7;
    const int bl15 = l & 15;
    const int jhi  = l >> 4;
    const int arow = rg * 32 + (l & 15);
    const int asw  = ((l & 15) & 7) << 4;

    float acc[2][4][4];
    #pragma unroll
    for (int m = 0; m < 2; m++)
        #pragma unroll
        for (int n = 0; n < 4; n++)
            #pragma unroll
            for (int q = 0; q < 4; q++) acc[m][n][q] = 0.f;

    #pragma unroll
    for (int ks = 0; ks < 4; ks++) {
        uint32_t ah[2][4], al[2][4];
        #pragma unroll
        for (int m = 0; m < 2; m++) {
            uint32_t aoff = (unsigned)(arow + m * 16) * 128 +
                            (((unsigned)(32 * ks + (l & 16))) ^ (unsigned)asw);
            ldmatrix_x4(ah[m], sbase + QSM_A_HI + aoff);
            ldmatrix_x4(al[m], sbase + QSM_A_LO + aoff);
        }
        uint32_t browoff = (unsigned)(16 * ks + bl15) * 256;
        #pragma unroll
        for (int np = 0; np < 2; np++) {
            uint32_t boff = ((unsigned)((cg * 4 + np * 2 + jhi) ^ lx)) << 4;
            uint32_t bh[4], blo[4];
            ldmatrix_x4t(bh,  sbase + QSM_B_HI + browoff + boff);
            ldmatrix_x4t(blo, sbase + QSM_B_LO + browoff + boff);
            #pragma unroll
            for (int m = 0; m < 2; m++) {
                mma16816(acc[m][np * 2],     ah[m], bh);
                mma16816(acc[m][np * 2 + 1], ah[m], bh + 2);
                mma16816(acc[m][np * 2],     al[m], bh);
                mma16816(acc[m][np * 2 + 1], al[m], bh + 2);
                mma16816(acc[m][np * 2],     ah[m], blo);
                mma16816(acc[m][np * 2 + 1], ah[m], blo + 2);
            }
        }
    }

    float2 bias[4];
    #pragma unroll
    for (int n = 0; n < 4; n++) {
        int col = cg * 32 + n * 8 + t2;
        bias[n] = make_float2(__ldg(Bv + col), __ldg(Bv + col + 1));
    }
    #pragma unroll
    for (int m = 0; m < 2; m++) {
        int row0 = m0 + rg * 32 + m * 16 + g;
        #pragma unroll
        for (int n = 0; n < 4; n++) {
            int col = cg * 32 + n * 8 + t2;
            if (row0 < NNODES)
                *(float2*)(out + (size_t)row0 * HD + col) =
                    make_float2(acc[m][n][0] + bias[n].x, acc[m][n][1] + bias[n].y);
            if (row0 + 8 < NNODES)
                *(float2*)(out + (size_t)(row0 + 8) * HD + col) =
                    make_float2(acc[m][n][2] + bias[n].x, acc[m][n][3] + bias[n].y);
        }
    }
}

// ---------------- K2: edge GEMM, BN=256, coalesced kq staging ---------------
// 1024 threads / 32 warps; warp = 32 rows x 1 head. 3-term hi/lo split.
// After MMA: stage kq = K[src]+Q[dst] coalesced into smem, epilogue reads
// kq from smem, writes scores back in place, then coalesced STG.128 to oE.
#define SM_A_HI 0
#define SM_A_LO 16384
#define SM_B_HI 32768
#define SM_B_LO 65536
#define SMEM_EDGE_TOTAL 98304
#define KQ_STRIDE 132

__global__ __launch_bounds__(1024, 1) void edge_kernel(
    const float* __restrict__ eattr, const int* __restrict__ eidx,
    const float* __restrict__ Eb, const float* __restrict__ Aw,
    float* __restrict__ outbuf)
{
    extern __shared__ char smem[];
    const uint32_t sbase = smem_u32(smem);
    const int t   = threadIdx.x;
    const int l   = t & 31;
    const int w   = t >> 5;
    const int m0  = blockIdx.x * 128;

    // ---- A tile: 128 edges x 64 K -> hi/lo bf16, swizzled (128B rows)
    #pragma unroll
    for (int it = 0; it < 2; it++) {
        int idx = it * 1024 + t;
        int row = idx >> 4;
        int c4  = (idx & 15) * 4;
        float4 v = __ldcs((const float4*)(eattr + (size_t)(m0 + row) * 64 + c4));
        unsigned int byte = (unsigned)row * 128 + (((unsigned)c4 * 2) ^ (((unsigned)row & 7) << 4));
        *(unsigned long long*)(smem + SM_A_HI + byte) = pack4_hi(v);
        *(unsigned long long*)(smem + SM_A_LO + byte) = pack4_hi(resid4(v));
    }
    // ---- B image copy (32KB each)
    {
        const ulonglong2* bh = (const ulonglong2*)g_Bh;
        const ulonglong2* bl = (const ulonglong2*)g_Bl;
        ulonglong2* dh = (ulonglong2*)(smem + SM_B_HI);
        ulonglong2* dl = (ulonglong2*)(smem + SM_B_LO);
        #pragma unroll
        for (int it = 0; it < 2; it++) {
            int idx = it * 1024 + t;
            dh[idx] = bh[idx];
            dl[idx] = bl[idx];
        }
    }
    __syncthreads();

    // ---- MMA: warp w -> rows 32*(w>>3)..+31, head (w&7)
    const int rg   = w >> 3;
    const int cg   = w & 7;
    const int g    = l >> 2;
    const int t2   = (l & 3) * 2;
    const int lx   = l & 7;
    const int bl15 = l & 15;
    const int jhi  = l >> 4;
    const int arow = rg * 32 + (l & 15);
    const int asw  = ((l & 15) & 7) << 4;

    float acc[2][4][4];
    #pragma unroll
    for (int m = 0; m < 2; m++)
        #pragma unroll
        for (int n = 0; n < 4; n++)
            #pragma unroll
            for (int q = 0; q < 4; q++) acc[m][n][q] = 0.f;

    #pragma unroll
    for (int ks = 0; ks < 4; ks++) {
        uint32_t ah[2][4], al[2][4];
        #pragma unroll
        for (int m = 0; m < 2; m++) {
            uint32_t aoff = (unsigned)(arow + m * 16) * 128 +
                            (((unsigned)(32 * ks + (l & 16))) ^ (unsigned)asw);
            ldmatrix_x4(ah[m], sbase + SM_A_HI + aoff);
            ldmatrix_x4(al[m], sbase + SM_A_LO + aoff);
        }
        uint32_t browoff = (unsigned)(16 * ks + bl15) * 512;   // 512B rows (256 cols)
        #pragma unroll
        for (int np = 0; np < 2; np++) {
            uint32_t boff = ((unsigned)((cg * 4 + np * 2 + jhi) ^ lx)) << 4;
            uint32_t bh[4], blo[4];
            ldmatrix_x4t(bh,  sbase + SM_B_HI + browoff + boff);
            ldmatrix_x4t(blo, sbase + SM_B_LO + browoff + boff);
            #pragma unroll
            for (int m = 0; m < 2; m++) {
                mma16816(acc[m][np * 2],     ah[m], bh);
                mma16816(acc[m][np * 2 + 1], ah[m], bh + 2);
                mma16816(acc[m][np * 2],     al[m], bh);
                mma16816(acc[m][np * 2 + 1], al[m], bh + 2);
                mma16816(acc[m][np * 2],     ah[m], blo);
                mma16816(acc[m][np * 2 + 1], ah[m], blo + 2);
            }
        }
    }

    __syncthreads();            // A/B smem dead; overlay kq[128][132]
    float* kqs = (float*)smem;

    // ---- stage kq = K[src] + Q[dst], fully coalesced (8 threads per row)
    {
        const int eL  = t >> 3;
        const int seg = t & 7;
        const int e   = m0 + eL;
        const float* Kr = g_K + (size_t)eidx[e] * HD;
        const float* Qr = g_Q + (size_t)eidx[NEDGES + e] * HD;
        float* row = kqs + eL * KQ_STRIDE;
        #pragma unroll
        for (int q = 0; q < 4; q++) {
            int f = (seg + q * 8) * 4;
            float4 kv = *(const float4*)(Kr + f);
            float4 qv = *(const float4*)(Qr + f);
            *(float4*)(row + f) = make_float4(kv.x + qv.x, kv.y + qv.y,
                                              kv.z + qv.z, kv.w + qv.w);
        }
    }
    __syncthreads();

    // ---- epilogue (kq from smem; scores written back in place) ----
    const int h    = cg;
    const int colK = h * 16;

    const float eb1a = __ldg(Eb + h * 32 + t2);
    const float eb1b = __ldg(Eb + h * 32 + t2 + 1);
    const float eb1c = __ldg(Eb + h * 32 + 8 + t2);
    const float eb1d = __ldg(Eb + h * 32 + 8 + t2 + 1);
    const float eb2a = __ldg(Eb + h * 32 + 16 + t2);
    const float eb2b = __ldg(Eb + h * 32 + 16 + t2 + 1);
    const float eb2c = __ldg(Eb + h * 32 + 24 + t2);
    const float eb2d = __ldg(Eb + h * 32 + 24 + t2 + 1);
    const float aw0 = __ldg(Aw + (t2)     * 8 + h);
    const float aw1 = __ldg(Aw + (t2 + 1) * 8 + h);
    const float aw8 = __ldg(Aw + (8 + t2)     * 8 + h);
    const float aw9 = __ldg(Aw + (8 + t2 + 1) * 8 + h);

    float apart[4];
    #pragma unroll
    for (int r = 0; r < 4; r++) {
        const int m  = r >> 1;
        const int qh = r & 1;
        const int rowl = rg * 32 + m * 16 + g + qh * 8;
        float* kqrow = kqs + rowl * KQ_STRIDE + colK;

        float a = 0.f;
        {
            float s1a = acc[m][0][qh * 2]     + eb1a;
            float s1b = acc[m][0][qh * 2 + 1] + eb1b;
            float s2a = acc[m][2][qh * 2]     + eb2a;
            float s2b = acc[m][2][qh * 2 + 1] + eb2b;
            float2 kq = *(const float2*)(kqrow + t2);
            float p0 = s1a * s2a, p1 = s1b * s2b;
            float sc0 = copysignf(sqrt_approx(fabsf(p0)), p0) + kq.x;
            float sc1 = copysignf(sqrt_approx(fabsf(p1)), p1) + kq.y;
            *(float2*)(kqrow + t2) = make_float2(sc0, sc1);
            a += sc0 * aw0 + sc1 * aw1;
        }
        {
            float s1a = acc[m][1][qh * 2]     + eb1c;
            float s1b = acc[m][1][qh * 2 + 1] + eb1d;
            float s2a = acc[m][3][qh * 2]     + eb2c;
            float s2b = acc[m][3][qh * 2 + 1] + eb2d;
            float2 kq = *(const float2*)(kqrow + 8 + t2);
            float p0 = s1a * s2a, p1 = s1b * s2b;
            float sc0 = copysignf(sqrt_approx(fabsf(p0)), p0) + kq.x;
            float sc1 = copysignf(sqrt_approx(fabsf(p1)), p1) + kq.y;
            *(float2*)(kqrow + 8 + t2) = make_float2(sc0, sc1);
            a += sc0 * aw8 + sc1 * aw9;
        }
        apart[r] = a;
    }

    #pragma unroll
    for (int r = 0; r < 4; r++) {
        apart[r] += __shfl_xor_sync(0xffffffffu, apart[r], 1);
        apart[r] += __shfl_xor_sync(0xffffffffu, apart[r], 2);
    }
    if ((l & 3) == 0) {
        #pragma unroll
        for (int r = 0; r < 4; r++) {
            const int e = m0 + rg * 32 + (r >> 1) * 16 + g + (r & 1) * 8;
            float a = fminf(fmaxf(apart[r], -5.0f), 5.0f);
            g_w[(size_t)e * 8 + h] = expf(a);
        }
    }

    __syncthreads();

    // ---- coalesced oE store (STG.128, streaming)
    {
        const int eL  = t >> 3;
        const int seg = t & 7;
        const float* row = kqs + eL * KQ_STRIDE;
        float* oEr = outbuf + (size_t)OUT_OE + (size_t)(m0 + eL) * HD;
        #pragma unroll
        for (int q = 0; q < 4; q++) {
            int f = (seg + q * 8) * 4;
            __stcs((float4*)(oEr + f), *(const float4*)(row + f));
        }
    }
}

// ---------------- K3: CSR build ---------------------------------------------
__global__ void zero_kernel()
{
    int i = blockIdx.x * blockDim.x + threadIdx.x;
    if (i < NNODES) g_deg[i] = 0;
}
__global__ void hist_kernel(const int* __restrict__ eidx)
{
    int e = blockIdx.x * blockDim.x + threadIdx.x;
    if (e < NEDGES) atomicAdd(&g_deg[eidx[NEDGES + e]], 1);
}
__global__ __launch_bounds__(SCAN_BLK) void scan1_kernel()
{
    __shared__ int warpsum[SCAN_BLK / 32];
    const int b = blockIdx.x, t = threadIdx.x;
    const int i = b * SCAN_BLK + t;
    int v = (i < NNODES) ? g_deg[i] : 0;
    int s = v;
    #pragma unroll
    for (int o = 1; o < 32; o <<= 1) {
        int u = __shfl_up_sync(0xffffffffu, s, o);
        if ((t & 31) >= o) s += u;
    }
    if ((t & 31) == 31) warpsum[t >> 5] = s;
    __syncthreads();
    if (t < SCAN_BLK / 32) {
        int ws = warpsum[t];
        #pragma unroll
        for (int o = 1; o < SCAN_BLK / 32; o <<= 1) {
            int u = __shfl_up_sync((1u << (SCAN_BLK / 32)) - 1u, ws, o);
            if (t >= o) ws += u;
        }
        warpsum[t] = ws;
    }
    __syncthreads();
    int excl = s - v + ((t >> 5) ? warpsum[(t >> 5) - 1] : 0);
    if (i < NNODES) g_off[i] = excl;
    if (t == SCAN_BLK - 1) g_bsum[b] = excl + v;
}
__global__ void scan2_kernel()
{
    __shared__ int ws[4];
    const int t = threadIdx.x;   // 128
    int v = (t < NSCB) ? g_bsum[t] : 0;
    int s = v;
    #pragma unroll
    for (int o = 1; o < 32; o <<= 1) {
        int u = __shfl_up_sync(0xffffffffu, s, o);
        if ((t & 31) >= o) s += u;
    }
    if ((t & 31) == 31) ws[t >> 5] = s;
    __syncthreads();
    if (t < 4) {
        int wv = ws[t];
        #pragma unroll
        for (int o = 1; o < 4; o <<= 1) {
            int u = __shfl_up_sync(0xfu, wv, o);
            if (t >= o) wv += u;
        }
        ws[t] = wv;
    }
    __syncthreads();
    int excl = s - v + ((t >> 5) ? ws[(t >> 5) - 1] : 0);
    if (t < NSCB) g_bpre[t] = excl;
    if (t == NSCB - 1) g_off[NNODES] = excl + v;
}
__global__ void scan3_kernel()
{
    int i = blockIdx.x * blockDim.x + threadIdx.x;
    if (i < NNODES) {
        int o = g_off[i] + g_bpre[i >> 8];
        g_off[i] = o;
        g_cursor[i] = o;
    }
}
__global__ void scatter_kernel(const int* __restrict__ eidx)
{
    int e = blockIdx.x * blockDim.x + threadIdx.x;
    if (e < NEDGES) {
        int dst = eidx[NEDGES + e];
        int p = atomicAdd(&g_cursor[dst], 1);
        g_csr[p] = make_int2(e, eidx[e]);
    }
}

// ---------------- K4: fused softmax + aggregation (R14 version) -------------
__global__ __launch_bounds__(128) void node_kernel(
    const float* __restrict__ VeRow,
    const float* __restrict__ oE,
    float* __restrict__ n_out)
{
    __shared__ int2  stage[128];
    __shared__ float rowS[8][17];
    const int n = blockIdx.x;
    const int t = threadIdx.x;
    const int h = t >> 4, c = t & 15;
    const int beg = g_off[n], end = g_off[n + 1];

    float den = 0.f, accV = 0.f, accR = 0.f;
    for (int base = beg; base < end; base += 128) {
        int cnt = min(128, end - base);
        __syncthreads();
        if (t < cnt) stage[t] = g_csr[base + t];
        __syncthreads();
        #pragma unroll 4
        for (int i = 0; i < cnt; i++) {
            int e   = stage[i].x;
            int src = stage[i].y;
            float wv = g_w[(size_t)e * 8 + h];
            den  += wv;
            accV += wv * g_V[(size_t)src * HD + t];
            accR += wv * __ldcs(oE + (size_t)e * HD + t);
        }
    }
    float inv = 1.f / (den + 1e-16f);

    rowS[h][c] = accR * inv;
    __syncthreads();
    float r = 0.f;
    #pragma unroll
    for (int d = 0; d < 16; d++)
        r += rowS[h][d] * VeRow[d * HD + h * 16 + c];

    n_out[(size_t)n * HD + t] = accV * inv + r;
}

// ---------------- launch -----------------------------------------------------
extern "C" void kernel_launch(void* const* d_in, const int* in_sizes, int n_in,
                              void* d_out, int out_size)
{
    const float* x     = (const float*)d_in[0];
    const float* eattr = (const float*)d_in[1];
    const int*   eidx  = (const int*)  d_in[2];
    const float* Qw = (const float*)d_in[3];  const float* Qb = (const float*)d_in[4];
    const float* Kw = (const float*)d_in[5];  const float* Kb = (const float*)d_in[6];
    const float* Ew = (const float*)d_in[7];  const float* Eb = (const float*)d_in[8];
    const float* Vw = (const float*)d_in[9];  const float* Vb = (const float*)d_in[10];
    const float* Aw = (const float*)d_in[11]; const float* VeRow = (const float*)d_in[12];
    float* out = (float*)d_out;

    cudaFuncSetAttribute(edge_kernel, cudaFuncAttributeMaxDynamicSharedMemorySize,
                         SMEM_EDGE_TOTAL);
    cudaFuncSetAttribute(qkv_kernel, cudaFuncAttributeMaxDynamicSharedMemorySize,
                         SMEM_QKV_TOTAL);

    cudaStream_t s = 0;
    cudaStream_t sideS;
    cudaEvent_t  evFork, evW, evB, evJoin;
    cudaStreamCreateWithFlags(&sideS, cudaStreamNonBlocking);
    cudaEventCreateWithFlags(&evFork, cudaEventDisableTiming);
    cudaEventCreateWithFlags(&evW,    cudaEventDisableTiming);
    cudaEventCreateWithFlags(&evB,    cudaEventDisableTiming);
    cudaEventCreateWithFlags(&evJoin, cudaEventDisableTiming);

    cudaEventRecord(evFork, s);
    cudaStreamWaitEvent(sideS, evFork, 0);

    // side: Ew image prep first (edge needs it), then CSR build, then V GEMM
    bprep_kernel<<<4, 256, 0, sideS>>>(Ew);
    cudaEventRecord(evB, sideS);
    zero_kernel<<<(NNODES + 255) / 256, 256, 0, sideS>>>();
    hist_kernel<<<(NEDGES + 255) / 256, 256, 0, sideS>>>(eidx);
    scan1_kernel<<<NSCB, SCAN_BLK, 0, sideS>>>();
    scan2_kernel<<<1, 128, 0, sideS>>>();
    scan3_kernel<<<(NNODES + 255) / 256, 256, 0, sideS>>>();
    scatter_kernel<<<(NEDGES + 255) / 256, 256, 0, sideS>>>(eidx);

    // main: weight prep + Q,K GEMMs
    wprep_kernel<<<3, 256, 0, s>>>(Qw, Kw, Vw);
    cudaEventRecord(evW, s);
    qkv_kernel<<<dim3((NNODES + 127) / 128, 2), 512, SMEM_QKV_TOTAL, s>>>(
        x, Qb, Kb, Vb, 0);                                      // Q, K

    // side: V GEMM after wprep
    cudaStreamWaitEvent(sideS, evW, 0);
    qkv_kernel<<<dim3((NNODES + 127) / 128, 1), 512, SMEM_QKV_TOTAL, sideS>>>(
        x, Qb, Kb, Vb, 2);                                      // V
    cudaEventRecord(evJoin, sideS);

    // main: edge GEMM (needs Q,K + Ew image), then node
    cudaStreamWaitEvent(s, evB, 0);
    edge_kernel<<<NEDGES / 128, 1024, SMEM_EDGE_TOTAL, s>>>(eattr, eidx, Eb, Aw, out);
    cudaStreamWaitEvent(s, evJoin, 0);
    node_kernel<<<NNODES, 128, 0, s>>>(VeRow, out + OUT_OE, out);
}